// round 3
// baseline (speedup 1.0000x reference)
#include <cuda_runtime.h>

#define T_ 64
#define B_ 128
#define L_ 64
#define E_ 256
#define H_ 32
#define N_ (T_*B_)

#define XS_STR 260
#define AS_STR 260
#define YT_STR 68
#define ATTN_SMEM ((64*XS_STR + 64*AS_STR + 64*YT_STR + 64 + 64 + 64 + 256) * 4)
#define LSTM_SMEM ((128*260 + 128*36 + 256 + 128 + 128 + 32 + 32) * 4)

__device__ float g_At[E_*E_];
__device__ float g_Ccm[E_*E_];
__device__ float g_hidden[(size_t)N_*E_];
__device__ int   g_mask_mode;

__global__ void detect_mask_kernel(const void* __restrict__ mask)
{
    const unsigned int* w = (const unsigned int*)mask;
    __shared__ int s_not01, s_notf;
    if (threadIdx.x == 0) { s_not01 = 0; s_notf = 0; }
    __syncthreads();
    int not01 = 0, notf = 0;
    for (int i = threadIdx.x; i < 131072; i += 256) {
        unsigned int v = w[i];
        if (v != 0u && v != 1u) not01 = 1;
        if (v != 0u && v != 0x3F800000u) notf = 1;
    }
    if (not01) atomicOr(&s_not01, 1);
    if (notf)  atomicOr(&s_notf, 1);
    __syncthreads();
    if (threadIdx.x == 0)
        g_mask_mode = (!s_not01) ? 1 : ((!s_notf) ? 2 : 0);
}

// blocks [0,256): At[j][e] = sum_f Wq[f,e]*Wk[f,j].
// blocks [256,512): Ccm[j][f] = (Wout@Wv)[f][j].
__global__ __launch_bounds__(256) void precompute_kernel(
    const float* __restrict__ in_proj, const float* __restrict__ out_proj)
{
    __shared__ float buf[E_];
    const int b = blockIdx.x, tid = threadIdx.x;
    if (b < E_) {
        const int j = b;
        float acc = 0.f;
        #pragma unroll 4
        for (int f = 0; f < E_; ++f)
            acc = fmaf(in_proj[f*E_ + tid], in_proj[(E_+f)*E_ + j], acc);
        g_At[j*E_ + tid] = acc;
    } else {
        const int f = b - E_;
        buf[tid] = out_proj[f*E_ + tid];
        __syncthreads();
        float acc = 0.f;
        #pragma unroll 4
        for (int e = 0; e < E_; ++e)
            acc = fmaf(buf[e], in_proj[(2*E_+e)*E_ + tid], acc);
        g_Ccm[tid*E_ + f] = acc;
    }
}

__global__ __launch_bounds__(256) void attn_kernel(
    const float* __restrict__ x, const void* __restrict__ mask)
{
    extern __shared__ float sm[];
    float* xs     = sm;                 // [64][260]
    float* As     = xs + 64*XS_STR;     // [64][260]
    float* yt     = As + 64*AS_STR;     // [64][68]  y tile, later S
    float* wsum   = yt + 64*YT_STR;     // [64]
    float* rowinv = wsum + 64;          // [64]
    float* dropf  = rowinv + 64;        // [64]
    float* zsh    = dropf + 64;         // [256]

    const int n = blockIdx.x, tid = threadIdx.x;
    const int lane = tid & 31, w = tid >> 5;
    const int lb = (w & 3) * 16 + ((lane >> 3) << 2);
    const int kb = ((w >> 2) << 5) + (lane & 7);

    {
        const float4* xg = (const float4*)(x + (size_t)n * (L_*E_));
        for (int i = tid; i < (L_*E_)/4; i += 256) {
            int l = i >> 6, c = i & 63;
            *(float4*)(xs + l*XS_STR + (c << 2)) = xg[i];
        }
    }
    if (tid < 64) {
        int mode = g_mask_mode;
        size_t idx = (size_t)n*L_ + tid;
        bool obs;
        if (mode == 1)      obs = ((const int*)mask)[idx] != 0;
        else if (mode == 2) obs = ((const float*)mask)[idx] != 0.0f;
        else                obs = ((const unsigned char*)mask)[idx] != 0;
        dropf[tid] = obs ? 0.f : 1.f;
        wsum[tid]  = 0.f;
    }

    float acc[4][4];
    #pragma unroll
    for (int i = 0; i < 4; ++i)
        #pragma unroll
        for (int j = 0; j < 4; ++j) acc[i][j] = 0.f;

    for (int tile = 0; tile < 4; ++tile) {
        __syncthreads();
        {
            const float4* ag = (const float4*)(g_At + tile*64*E_);
            for (int i = tid; i < (64*E_)/4; i += 256) {
                int j = i >> 6, c = i & 63;
                *(float4*)(As + j*AS_STR + (c << 2)) = ag[i];
            }
        }
        __syncthreads();
        {   // yt[l][j] = sum_e xs[l][e] * As[j][e]
            float ya[4][4];
            #pragma unroll
            for (int i = 0; i < 4; ++i)
                #pragma unroll
                for (int j = 0; j < 4; ++j) ya[i][j] = 0.f;
            #pragma unroll 4
            for (int e4 = 0; e4 < 64; ++e4) {
                float4 xv[4], av[4];
                #pragma unroll
                for (int il = 0; il < 4; ++il)
                    xv[il] = *(const float4*)(xs + (lb+il)*XS_STR + (e4 << 2));
                #pragma unroll
                for (int jl = 0; jl < 4; ++jl)
                    av[jl] = *(const float4*)(As + (kb + (jl<<3))*AS_STR + (e4 << 2));
                #pragma unroll
                for (int il = 0; il < 4; ++il)
                    #pragma unroll
                    for (int jl = 0; jl < 4; ++jl) {
                        ya[il][jl] = fmaf(xv[il].x, av[jl].x, ya[il][jl]);
                        ya[il][jl] = fmaf(xv[il].y, av[jl].y, ya[il][jl]);
                        ya[il][jl] = fmaf(xv[il].z, av[jl].z, ya[il][jl]);
                        ya[il][jl] = fmaf(xv[il].w, av[jl].w, ya[il][jl]);
                    }
            }
            #pragma unroll
            for (int il = 0; il < 4; ++il)
                #pragma unroll
                for (int jl = 0; jl < 4; ++jl)
                    yt[(lb+il)*YT_STR + kb + (jl<<3)] = ya[il][jl];
        }
        __syncthreads();
        {   // acc[l][k] += sum_j yt[l][j] * xs[k][tile*64+j]
            const int cb = tile << 6;
            #pragma unroll 4
            for (int j4 = 0; j4 < 16; ++j4) {
                float4 yv[4], xv[4];
                #pragma unroll
                for (int il = 0; il < 4; ++il)
                    yv[il] = *(const float4*)(yt + (lb+il)*YT_STR + (j4 << 2));
                #pragma unroll
                for (int kl = 0; kl < 4; ++kl)
                    xv[kl] = *(const float4*)(xs + (kb + (kl<<3))*XS_STR + cb + (j4 << 2));
                #pragma unroll
                for (int il = 0; il < 4; ++il)
                    #pragma unroll
                    for (int kl = 0; kl < 4; ++kl) {
                        acc[il][kl] = fmaf(yv[il].x, xv[kl].x, acc[il][kl]);
                        acc[il][kl] = fmaf(yv[il].y, xv[kl].y, acc[il][kl]);
                        acc[il][kl] = fmaf(yv[il].z, xv[kl].z, acc[il][kl]);
                        acc[il][kl] = fmaf(yv[il].w, xv[kl].w, acc[il][kl]);
                    }
            }
        }
    }
    __syncthreads();
    #pragma unroll
    for (int il = 0; il < 4; ++il) {
        float dl = dropf[lb+il];
        #pragma unroll
        for (int kl = 0; kl < 4; ++kl) {
            float dk = dropf[kb + (kl<<3)];
            float s = acc[il][kl] * 0.0625f;
            if (dl * dk != 0.f) s = -1e9f;
            yt[(lb+il)*YT_STR + kb + (kl<<3)] = s;
        }
    }
    __syncthreads();
    {   // softmax over k (4 lanes per row)
        int r = tid >> 2, part = tid & 3;
        float* Srow = yt + r*YT_STR + (part << 4);
        float m = -1e30f;
        #pragma unroll
        for (int kk = 0; kk < 16; ++kk) m = fmaxf(m, Srow[kk]);
        m = fmaxf(m, __shfl_xor_sync(0xffffffffu, m, 1));
        m = fmaxf(m, __shfl_xor_sync(0xffffffffu, m, 2));
        float ssum = 0.f;
        #pragma unroll
        for (int kk = 0; kk < 16; ++kk) {
            float p = __expf(Srow[kk] - m);
            Srow[kk] = p; ssum += p;
        }
        ssum += __shfl_xor_sync(0xffffffffu, ssum, 1);
        ssum += __shfl_xor_sync(0xffffffffu, ssum, 2);
        if (part == 0) rowinv[r] = 1.f / ssum;
    }
    __syncthreads();
    {   // column sums of probs
        int k = tid & 63, seg = tid >> 6;
        float p = 0.f;
        #pragma unroll
        for (int li = 0; li < 16; ++li) {
            int l = (seg << 4) + li;
            p = fmaf(yt[l*YT_STR + k], rowinv[l], p);
        }
        atomicAdd(&wsum[k], p);
    }
    __syncthreads();
    {
        float z = 0.f;
        #pragma unroll 8
        for (int k = 0; k < 64; ++k) z = fmaf(wsum[k], xs[k*XS_STR + tid], z);
        zsh[tid] = z;
    }
    __syncthreads();
    {
        float hacc = 0.f;
        const float* cp = g_Ccm + tid;
        #pragma unroll 8
        for (int j = 0; j < E_; ++j) hacc = fmaf(zsh[j], cp[(size_t)j*E_], hacc);
        g_hidden[(size_t)n*E_ + tid] = hacc;
    }
}

__global__ __launch_bounds__(128) void lstm_kernel(
    const float* __restrict__ done, const float* __restrict__ h0,
    const float* __restrict__ c0,
    const float* __restrict__ w_ih, const float* __restrict__ w_hh,
    const float* __restrict__ b_ih, const float* __restrict__ b_hh,
    const float* __restrict__ critic_w, const float* __restrict__ critic_b,
    float* __restrict__ out)
{
    extern __shared__ float sm[];
    float* wih  = sm;                // [128][260]
    float* whh  = wih + 128*260;     // [128][36]
    float* xrow = whh + 128*36;      // [256]
    float* bias = xrow + 256;        // [128]
    float* garr = bias + 128;        // [128]
    float* hsm  = garr + 128;        // [32]
    float* csm  = hsm + 32;          // [32]

    const int env = blockIdx.x, tid = threadIdx.x;

    for (int i = tid; i < 128*256; i += 128)
        wih[(i >> 8)*260 + (i & 255)] = w_ih[i];
    for (int i = tid; i < 128*32; i += 128)
        whh[(i >> 5)*36 + (i & 31)] = w_hh[i];
    bias[tid] = b_ih[tid] + b_hh[tid];
    if (tid < 32) { hsm[tid] = h0[env*H_ + tid]; csm[tid] = c0[env*H_ + tid]; }
    const float cw = (tid < 32) ? critic_w[tid] : 0.f;
    const float cb = critic_b[0];
    __syncthreads();

    const float4* wr = (const float4*)(wih + tid*260);
    const float4* wh = (const float4*)(whh + tid*36);

    for (int t = 0; t < T_; ++t) {
        const int row = t*B_ + env;
        const float keep = 1.f - done[row];
        if (tid < 32) { hsm[tid] *= keep; csm[tid] *= keep; }
        {
            const float* hr = g_hidden + (size_t)row*E_;
            xrow[tid]       = hr[tid];
            xrow[tid + 128] = hr[tid + 128];
        }
        __syncthreads();

        float acc = bias[tid];
        const float4* xr = (const float4*)xrow;
        #pragma unroll 8
        for (int e4 = 0; e4 < 64; ++e4) {
            float4 a = wr[e4], b = xr[e4];
            acc = fmaf(a.x, b.x, acc); acc = fmaf(a.y, b.y, acc);
            acc = fmaf(a.z, b.z, acc); acc = fmaf(a.w, b.w, acc);
        }
        const float4* hv = (const float4*)hsm;
        #pragma unroll
        for (int j4 = 0; j4 < 8; ++j4) {
            float4 a = wh[j4], b = hv[j4];
            acc = fmaf(a.x, b.x, acc); acc = fmaf(a.y, b.y, acc);
            acc = fmaf(a.z, b.z, acc); acc = fmaf(a.w, b.w, acc);
        }
        garr[tid] = (tid >= 64 && tid < 96) ? tanhf(acc)
                                            : (1.f / (1.f + __expf(-acc)));
        __syncthreads();

        if (tid < 32) {
            float c = fmaf(garr[32 + tid], csm[tid], garr[tid] * garr[64 + tid]);
            float h = garr[96 + tid] * tanhf(c);
            csm[tid] = c; hsm[tid] = h;
            float p = h * cw;
            p += __shfl_xor_sync(0xffffffffu, p, 16);
            p += __shfl_xor_sync(0xffffffffu, p, 8);
            p += __shfl_xor_sync(0xffffffffu, p, 4);
            p += __shfl_xor_sync(0xffffffffu, p, 2);
            p += __shfl_xor_sync(0xffffffffu, p, 1);
            if (tid == 0) out[row] = p + cb;
        }
        __syncthreads();
    }
}

extern "C" void kernel_launch(void* const* d_in, const int* in_sizes, int n_in,
                              void* d_out, int out_size)
{
    const float* x        = (const float*)d_in[0];
    const float* done     = (const float*)d_in[1];
    const void*  mask     = d_in[2];
    const float* h0       = (const float*)d_in[3];
    const float* c0       = (const float*)d_in[4];
    const float* in_proj  = (const float*)d_in[5];
    const float* out_proj = (const float*)d_in[6];
    const float* w_ih     = (const float*)d_in[7];
    const float* w_hh     = (const float*)d_in[8];
    const float* b_ih     = (const float*)d_in[9];
    const float* b_hh     = (const float*)d_in[10];
    const float* critic_w = (const float*)d_in[11];
    const float* critic_b = (const float*)d_in[12];
    float* out = (float*)d_out;

    cudaFuncSetAttribute(attn_kernel, cudaFuncAttributeMaxDynamicSharedMemorySize, ATTN_SMEM);
    cudaFuncSetAttribute(lstm_kernel, cudaFuncAttributeMaxDynamicSharedMemorySize, LSTM_SMEM);

    detect_mask_kernel<<<1, 256>>>(mask);
    precompute_kernel<<<2*E_, 256>>>(in_proj, out_proj);
    attn_kernel<<<N_, 256, ATTN_SMEM>>>(x, mask);
    lstm_kernel<<<B_, 128, LSTM_SMEM>>>(done, h0, c0, w_ih, w_hh, b_ih, b_hh,
                                        critic_w, critic_b, out);
}

// round 4
// speedup vs baseline: 1.0002x; 1.0002x over previous
#include <cuda_runtime.h>

#define T_ 64
#define B_ 128
#define L_ 64
#define E_ 256
#define H_ 32
#define N_ (T_*B_)

#define XS_STR 260
#define AS_STR 260
#define YT_STR 68
#define ATTN_SMEM ((64*XS_STR + 64*AS_STR + 64*YT_STR + 64 + 64 + 64 + 256) * 4)
#define LSTM_SMEM ((128*260 + 128*36 + 256 + 128 + 128 + 32 + 32) * 4)

__device__ float g_At[E_*E_];
__device__ float g_Ccm[E_*E_];
__device__ float g_hidden[(size_t)N_*E_];
__device__ int   g_mask_mode;

__global__ void detect_mask_kernel(const void* __restrict__ mask)
{
    const unsigned int* w = (const unsigned int*)mask;
    __shared__ int s_not01, s_notf;
    if (threadIdx.x == 0) { s_not01 = 0; s_notf = 0; }
    __syncthreads();
    int not01 = 0, notf = 0;
    for (int i = threadIdx.x; i < 131072; i += 256) {
        unsigned int v = w[i];
        if (v != 0u && v != 1u) not01 = 1;
        if (v != 0u && v != 0x3F800000u) notf = 1;
    }
    if (not01) atomicOr(&s_not01, 1);
    if (notf)  atomicOr(&s_notf, 1);
    __syncthreads();
    if (threadIdx.x == 0)
        g_mask_mode = (!s_not01) ? 1 : ((!s_notf) ? 2 : 0);
}

// blocks [0,256): At[j][e] = sum_f Wq[f,e]*Wk[f,j].
// blocks [256,512): Ccm[j][f] = (Wout@Wv)[f][j].
__global__ __launch_bounds__(256) void precompute_kernel(
    const float* __restrict__ in_proj, const float* __restrict__ out_proj)
{
    __shared__ float buf[E_];
    const int b = blockIdx.x, tid = threadIdx.x;
    if (b < E_) {
        const int j = b;
        float acc = 0.f;
        #pragma unroll 4
        for (int f = 0; f < E_; ++f)
            acc = fmaf(in_proj[f*E_ + tid], in_proj[(E_+f)*E_ + j], acc);
        g_At[j*E_ + tid] = acc;
    } else {
        const int f = b - E_;
        buf[tid] = out_proj[f*E_ + tid];
        __syncthreads();
        float acc = 0.f;
        #pragma unroll 4
        for (int e = 0; e < E_; ++e)
            acc = fmaf(buf[e], in_proj[(2*E_+e)*E_ + tid], acc);
        g_Ccm[tid*E_ + f] = acc;
    }
}

__global__ __launch_bounds__(256) void attn_kernel(
    const float* __restrict__ x, const void* __restrict__ mask)
{
    extern __shared__ float sm[];
    float* xs     = sm;                 // [64][260]
    float* As     = xs + 64*XS_STR;     // [64][260]
    float* yt     = As + 64*AS_STR;     // [64][68]  y tile, later S
    float* wsum   = yt + 64*YT_STR;     // [64]
    float* rowinv = wsum + 64;          // [64]
    float* dropf  = rowinv + 64;        // [64]
    float* zsh    = dropf + 64;         // [256]

    const int n = blockIdx.x, tid = threadIdx.x;
    const int lane = tid & 31, w = tid >> 5;
    const int lb = (w & 3) * 16 + ((lane >> 3) << 2);
    const int kb = ((w >> 2) << 5) + (lane & 7);

    {
        const float4* xg = (const float4*)(x + (size_t)n * (L_*E_));
        for (int i = tid; i < (L_*E_)/4; i += 256) {
            int l = i >> 6, c = i & 63;
            *(float4*)(xs + l*XS_STR + (c << 2)) = xg[i];
        }
    }
    if (tid < 64) {
        int mode = g_mask_mode;
        size_t idx = (size_t)n*L_ + tid;
        bool obs;
        if (mode == 1)      obs = ((const int*)mask)[idx] != 0;
        else if (mode == 2) obs = ((const float*)mask)[idx] != 0.0f;
        else                obs = ((const unsigned char*)mask)[idx] != 0;
        dropf[tid] = obs ? 0.f : 1.f;
        wsum[tid]  = 0.f;
    }

    float acc[4][4];
    #pragma unroll
    for (int i = 0; i < 4; ++i)
        #pragma unroll
        for (int j = 0; j < 4; ++j) acc[i][j] = 0.f;

    for (int tile = 0; tile < 4; ++tile) {
        __syncthreads();
        {
            const float4* ag = (const float4*)(g_At + tile*64*E_);
            for (int i = tid; i < (64*E_)/4; i += 256) {
                int j = i >> 6, c = i & 63;
                *(float4*)(As + j*AS_STR + (c << 2)) = ag[i];
            }
        }
        __syncthreads();
        {   // yt[l][j] = sum_e xs[l][e] * As[j][e]
            float ya[4][4];
            #pragma unroll
            for (int i = 0; i < 4; ++i)
                #pragma unroll
                for (int j = 0; j < 4; ++j) ya[i][j] = 0.f;
            #pragma unroll 4
            for (int e4 = 0; e4 < 64; ++e4) {
                float4 xv[4], av[4];
                #pragma unroll
                for (int il = 0; il < 4; ++il)
                    xv[il] = *(const float4*)(xs + (lb+il)*XS_STR + (e4 << 2));
                #pragma unroll
                for (int jl = 0; jl < 4; ++jl)
                    av[jl] = *(const float4*)(As + (kb + (jl<<3))*AS_STR + (e4 << 2));
                #pragma unroll
                for (int il = 0; il < 4; ++il)
                    #pragma unroll
                    for (int jl = 0; jl < 4; ++jl) {
                        ya[il][jl] = fmaf(xv[il].x, av[jl].x, ya[il][jl]);
                        ya[il][jl] = fmaf(xv[il].y, av[jl].y, ya[il][jl]);
                        ya[il][jl] = fmaf(xv[il].z, av[jl].z, ya[il][jl]);
                        ya[il][jl] = fmaf(xv[il].w, av[jl].w, ya[il][jl]);
                    }
            }
            #pragma unroll
            for (int il = 0; il < 4; ++il)
                #pragma unroll
                for (int jl = 0; jl < 4; ++jl)
                    yt[(lb+il)*YT_STR + kb + (jl<<3)] = ya[il][jl];
        }
        __syncthreads();
        {   // acc[l][k] += sum_j yt[l][j] * xs[k][tile*64+j]
            const int cb = tile << 6;
            #pragma unroll 4
            for (int j4 = 0; j4 < 16; ++j4) {
                float4 yv[4], xv[4];
                #pragma unroll
                for (int il = 0; il < 4; ++il)
                    yv[il] = *(const float4*)(yt + (lb+il)*YT_STR + (j4 << 2));
                #pragma unroll
                for (int kl = 0; kl < 4; ++kl)
                    xv[kl] = *(const float4*)(xs + (kb + (kl<<3))*XS_STR + cb + (j4 << 2));
                #pragma unroll
                for (int il = 0; il < 4; ++il)
                    #pragma unroll
                    for (int kl = 0; kl < 4; ++kl) {
                        acc[il][kl] = fmaf(yv[il].x, xv[kl].x, acc[il][kl]);
                        acc[il][kl] = fmaf(yv[il].y, xv[kl].y, acc[il][kl]);
                        acc[il][kl] = fmaf(yv[il].z, xv[kl].z, acc[il][kl]);
                        acc[il][kl] = fmaf(yv[il].w, xv[kl].w, acc[il][kl]);
                    }
            }
        }
    }
    __syncthreads();
    #pragma unroll
    for (int il = 0; il < 4; ++il) {
        float dl = dropf[lb+il];
        #pragma unroll
        for (int kl = 0; kl < 4; ++kl) {
            float dk = dropf[kb + (kl<<3)];
            float s = acc[il][kl] * 0.0625f;
            if (dl * dk != 0.f) s = -1e9f;
            yt[(lb+il)*YT_STR + kb + (kl<<3)] = s;
        }
    }
    __syncthreads();
    {   // softmax over k (4 lanes per row)
        int r = tid >> 2, part = tid & 3;
        float* Srow = yt + r*YT_STR + (part << 4);
        float m = -1e30f;
        #pragma unroll
        for (int kk = 0; kk < 16; ++kk) m = fmaxf(m, Srow[kk]);
        m = fmaxf(m, __shfl_xor_sync(0xffffffffu, m, 1));
        m = fmaxf(m, __shfl_xor_sync(0xffffffffu, m, 2));
        float ssum = 0.f;
        #pragma unroll
        for (int kk = 0; kk < 16; ++kk) {
            float p = __expf(Srow[kk] - m);
            Srow[kk] = p; ssum += p;
        }
        ssum += __shfl_xor_sync(0xffffffffu, ssum, 1);
        ssum += __shfl_xor_sync(0xffffffffu, ssum, 2);
        if (part == 0) rowinv[r] = 1.f / ssum;
    }
    __syncthreads();
    {   // column sums of probs
        int k = tid & 63, seg = tid >> 6;
        float p = 0.f;
        #pragma unroll
        for (int li = 0; li < 16; ++li) {
            int l = (seg << 4) + li;
            p = fmaf(yt[l*YT_STR + k], rowinv[l], p);
        }
        atomicAdd(&wsum[k], p);
    }
    __syncthreads();
    {
        float z = 0.f;
        #pragma unroll 8
        for (int k = 0; k < 64; ++k) z = fmaf(wsum[k], xs[k*XS_STR + tid], z);
        zsh[tid] = z;
    }
    __syncthreads();
    {
        float hacc = 0.f;
        const float* cp = g_Ccm + tid;
        #pragma unroll 8
        for (int j = 0; j < E_; ++j) hacc = fmaf(zsh[j], cp[(size_t)j*E_], hacc);
        g_hidden[(size_t)n*E_ + tid] = hacc;
    }
}

__global__ __launch_bounds__(128) void lstm_kernel(
    const float* __restrict__ done, const float* __restrict__ h0,
    const float* __restrict__ c0,
    const float* __restrict__ w_ih, const float* __restrict__ w_hh,
    const float* __restrict__ b_ih, const float* __restrict__ b_hh,
    const float* __restrict__ critic_w, const float* __restrict__ critic_b,
    float* __restrict__ out)
{
    extern __shared__ float sm[];
    float* wih  = sm;                // [128][260]
    float* whh  = wih + 128*260;     // [128][36]
    float* xrow = whh + 128*36;      // [256]
    float* bias = xrow + 256;        // [128]
    float* garr = bias + 128;        // [128]
    float* hsm  = garr + 128;        // [32]
    float* csm  = hsm + 32;          // [32]

    const int env = blockIdx.x, tid = threadIdx.x;

    for (int i = tid; i < 128*256; i += 128)
        wih[(i >> 8)*260 + (i & 255)] = w_ih[i];
    for (int i = tid; i < 128*32; i += 128)
        whh[(i >> 5)*36 + (i & 31)] = w_hh[i];
    bias[tid] = b_ih[tid] + b_hh[tid];
    if (tid < 32) { hsm[tid] = h0[env*H_ + tid]; csm[tid] = c0[env*H_ + tid]; }
    const float cw = (tid < 32) ? critic_w[tid] : 0.f;
    const float cb = critic_b[0];
    __syncthreads();

    const float4* wr = (const float4*)(wih + tid*260);
    const float4* wh = (const float4*)(whh + tid*36);

    for (int t = 0; t < T_; ++t) {
        const int row = t*B_ + env;
        const float keep = 1.f - done[row];
        if (tid < 32) { hsm[tid] *= keep; csm[tid] *= keep; }
        {
            const float* hr = g_hidden + (size_t)row*E_;
            xrow[tid]       = hr[tid];
            xrow[tid + 128] = hr[tid + 128];
        }
        __syncthreads();

        float acc = bias[tid];
        const float4* xr = (const float4*)xrow;
        #pragma unroll 8
        for (int e4 = 0; e4 < 64; ++e4) {
            float4 a = wr[e4], b = xr[e4];
            acc = fmaf(a.x, b.x, acc); acc = fmaf(a.y, b.y, acc);
            acc = fmaf(a.z, b.z, acc); acc = fmaf(a.w, b.w, acc);
        }
        const float4* hv = (const float4*)hsm;
        #pragma unroll
        for (int j4 = 0; j4 < 8; ++j4) {
            float4 a = wh[j4], b = hv[j4];
            acc = fmaf(a.x, b.x, acc); acc = fmaf(a.y, b.y, acc);
            acc = fmaf(a.z, b.z, acc); acc = fmaf(a.w, b.w, acc);
        }
        garr[tid] = (tid >= 64 && tid < 96) ? tanhf(acc)
                                            : (1.f / (1.f + __expf(-acc)));
        __syncthreads();

        if (tid < 32) {
            float c = fmaf(garr[32 + tid], csm[tid], garr[tid] * garr[64 + tid]);
            float h = garr[96 + tid] * tanhf(c);
            csm[tid] = c; hsm[tid] = h;
            float p = h * cw;
            p += __shfl_xor_sync(0xffffffffu, p, 16);
            p += __shfl_xor_sync(0xffffffffu, p, 8);
            p += __shfl_xor_sync(0xffffffffu, p, 4);
            p += __shfl_xor_sync(0xffffffffu, p, 2);
            p += __shfl_xor_sync(0xffffffffu, p, 1);
            if (tid == 0) out[row] = p + cb;
        }
        __syncthreads();
    }
}

extern "C" void kernel_launch(void* const* d_in, const int* in_sizes, int n_in,
                              void* d_out, int out_size)
{
    const float* x        = (const float*)d_in[0];
    const float* done     = (const float*)d_in[1];
    const void*  mask     = d_in[2];
    const float* h0       = (const float*)d_in[3];
    const float* c0       = (const float*)d_in[4];
    const float* in_proj  = (const float*)d_in[5];
    const float* out_proj = (const float*)d_in[6];
    const float* w_ih     = (const float*)d_in[7];
    const float* w_hh     = (const float*)d_in[8];
    const float* b_ih     = (const float*)d_in[9];
    const float* b_hh     = (const float*)d_in[10];
    const float* critic_w = (const float*)d_in[11];
    const float* critic_b = (const float*)d_in[12];
    float* out = (float*)d_out;

    cudaFuncSetAttribute(attn_kernel, cudaFuncAttributeMaxDynamicSharedMemorySize, ATTN_SMEM);
    cudaFuncSetAttribute(lstm_kernel, cudaFuncAttributeMaxDynamicSharedMemorySize, LSTM_SMEM);

    detect_mask_kernel<<<1, 256>>>(mask);
    precompute_kernel<<<2*E_, 256>>>(in_proj, out_proj);
    attn_kernel<<<N_, 256, ATTN_SMEM>>>(x, mask);
    lstm_kernel<<<B_, 128, LSTM_SMEM>>>(done, h0, c0, w_ih, w_hh, b_ih, b_hh,
                                        critic_w, critic_b, out);
}

// round 10
// speedup vs baseline: 1.6889x; 1.6886x over previous
#include <cuda_runtime.h>
#include <cuda_bf16.h>
#include <cstdint>

#define T_ 64
#define B_ 128
#define L_ 64
#define E_ 256
#define H_ 32
#define N_ (T_*B_)

// ---- attn SMEM layout (bytes). X/Y rows: 256 bf16 = 512B, padded to 528B ----
#define XROW 528
#define XH_OFF   0                       // 64 x 528
#define XL_OFF   33792
#define YH_OFF   67584
#define YL_OFF   101376
#define AT_OFF   135168                  // 2 bufs x (hi 12288 + lo 12288)
#define AT_BUF   24576
#define AT_LO    12288
#define PROB_OFF AT_OFF                  // reuse: 64 x 68 f32 = 17408
#define DROPF_OFF 184320                 // 64 f32
#define WSUM_OFF  184576                 // 64 f32
#define RINV_OFF  184832                 // 64 f32
#define ATTN_SMEM 185088

#define LSTM_SMEM ((128*260 + 128*36 + 256 + 128 + 128 + 32 + 32) * 4)

__device__ __nv_bfloat16 g_At_hi[E_*E_];
__device__ __nv_bfloat16 g_At_lo[E_*E_];
__device__ float g_Ccm[E_*E_];
__device__ float g_z[(size_t)N_*E_];
__device__ float g_hidden[(size_t)N_*E_];
__device__ int   g_mask_mode;

// ---------------- helpers ----------------
__device__ __forceinline__ uint32_t smem_u32(const void* p) {
    uint32_t a;
    asm("{ .reg .u64 t; cvta.to.shared.u64 t, %1; cvt.u32.u64 %0, t; }"
        : "=r"(a) : "l"(p));
    return a;
}
__device__ __forceinline__ uint32_t lds32(uint32_t a) {
    uint32_t v;
    asm volatile("ld.shared.b32 %0, [%1];" : "=r"(v) : "r"(a));
    return v;
}
__device__ __forceinline__ void sts32(uint32_t a, uint32_t v) {
    asm volatile("st.shared.b32 [%0], %1;" :: "r"(a), "r"(v));
}
__device__ __forceinline__ void sts64(uint32_t a, uint32_t v0, uint32_t v1) {
    asm volatile("st.shared.v2.b32 [%0], {%1, %2};" :: "r"(a), "r"(v0), "r"(v1));
}
#define CP_ASYNC16(dst, src) \
    asm volatile("cp.async.ca.shared.global [%0], [%1], 16;" :: "r"(dst), "l"(src))
#define CP_COMMIT() asm volatile("cp.async.commit_group;" ::: "memory")
#define CP_WAIT0()  asm volatile("cp.async.wait_group 0;" ::: "memory")

// D += A * B^T  (m16n8k16, bf16 in, f32 accum)
__device__ __forceinline__ void mma16816(float* d, const uint32_t* a, const uint32_t* b) {
    asm volatile(
        "mma.sync.aligned.m16n8k16.row.col.f32.bf16.bf16.f32 "
        "{%0,%1,%2,%3}, {%4,%5,%6,%7}, {%8,%9}, {%0,%1,%2,%3};"
        : "+f"(d[0]), "+f"(d[1]), "+f"(d[2]), "+f"(d[3])
        : "r"(a[0]), "r"(a[1]), "r"(a[2]), "r"(a[3]), "r"(b[0]), "r"(b[1]));
}

__device__ __forceinline__ uint32_t pack_hi(float a, float b, float& ra, float& rb) {
    __nv_bfloat162 t = __floats2bfloat162_rn(a, b);
    ra = a - __low2float(t);
    rb = b - __high2float(t);
    return *(uint32_t*)&t;
}
__device__ __forceinline__ uint32_t pack_lo(float a, float b) {
    __nv_bfloat162 t = __floats2bfloat162_rn(a, b);
    return *(uint32_t*)&t;
}

// ---------------------------------------------------------------------------
__global__ void detect_mask_kernel(const void* __restrict__ mask)
{
    const unsigned int* w = (const unsigned int*)mask;
    __shared__ int s_not01, s_notf;
    if (threadIdx.x == 0) { s_not01 = 0; s_notf = 0; }
    __syncthreads();
    int not01 = 0, notf = 0;
    for (int i = threadIdx.x; i < 131072; i += 256) {
        unsigned int v = w[i];
        if (v != 0u && v != 1u) not01 = 1;
        if (v != 0u && v != 0x3F800000u) notf = 1;
    }
    if (not01) atomicOr(&s_not01, 1);
    if (notf)  atomicOr(&s_notf, 1);
    __syncthreads();
    if (threadIdx.x == 0)
        g_mask_mode = (!s_not01) ? 1 : ((!s_notf) ? 2 : 0);
}

// blocks [0,256): At[j][e] = sum_f Wq[f,e]*Wk[f,j] -> bf16 hi/lo
// blocks [256,512): Ccm[j][f] = (Wout@Wv)[f][j]
__global__ __launch_bounds__(256) void precompute_kernel(
    const float* __restrict__ in_proj, const float* __restrict__ out_proj)
{
    __shared__ float buf[E_];
    const int b = blockIdx.x, tid = threadIdx.x;
    if (b < E_) {
        const int j = b;
        float acc = 0.f;
        #pragma unroll 4
        for (int f = 0; f < E_; ++f)
            acc = fmaf(in_proj[f*E_ + tid], in_proj[(E_+f)*E_ + j], acc);
        __nv_bfloat16 h = __float2bfloat16_rn(acc);
        g_At_hi[j*E_ + tid] = h;
        g_At_lo[j*E_ + tid] = __float2bfloat16_rn(acc - __bfloat162float(h));
    } else {
        const int f = b - E_;
        buf[tid] = out_proj[f*E_ + tid];
        __syncthreads();
        float acc = 0.f;
        #pragma unroll 4
        for (int e = 0; e < E_; ++e)
            acc = fmaf(buf[e], in_proj[(2*E_+e)*E_ + tid], acc);
        g_Ccm[tid*E_ + f] = acc;
    }
}

// ---------------------------------------------------------------------------
// Attention, one row n per block, HMMA bf16-split.
__global__ __launch_bounds__(256, 1) void attn_mma_kernel(
    const float* __restrict__ x, const void* __restrict__ mask)
{
    extern __shared__ char sm[];
    const uint32_t sb = smem_u32(sm);
    const int tid = threadIdx.x;
    const int w = tid >> 5, lane = tid & 31;
    const int qr = lane >> 2, qc = lane & 3;
    const int m0 = (w & 3) * 16;            // m-tile base row
    const int nhalf = (w >> 2) * 128;       // GEMM1 n base
    const int n = blockIdx.x;

    float* dropf  = (float*)(sm + DROPF_OFF);
    float* wsm    = (float*)(sm + WSUM_OFF);
    float* rowinv = (float*)(sm + RINV_OFF);

    // --- prologue: issue At slice 0 (overlaps X load/split) ---
    #pragma unroll
    for (int it = 0; it < 2; ++it) {
        int i = tid + it*256;
        int j = i >> 1, half = i & 1;
        uint32_t d = sb + AT_OFF + j*48 + half*16;
        CP_ASYNC16(d,         g_At_hi + j*E_ + half*8);
        CP_ASYNC16(d + AT_LO, g_At_lo + j*E_ + half*8);
    }
    CP_COMMIT();

    // --- mask + wsum init ---
    if (tid < 64) {
        int mode = g_mask_mode;
        size_t idx = (size_t)n * L_ + tid;
        bool obs;
        if (mode == 1)      obs = ((const int*)mask)[idx] != 0;
        else if (mode == 2) obs = ((const float*)mask)[idx] != 0.0f;
        else                obs = ((const unsigned char*)mask)[idx] != 0;
        dropf[tid] = obs ? 0.f : 1.f;
        wsm[tid] = 0.f;
    }

    // --- load X[n] (64x256 f32), split to bf16 hi/lo ---
    {
        const float4* xg = (const float4*)(x + (size_t)n * (L_*E_));
        for (int i = tid; i < 4096; i += 256) {
            float4 v = xg[i];
            int row = i >> 6, c4 = i & 63;
            float la, lb, lc, ld;
            uint32_t h01 = pack_hi(v.x, v.y, la, lb);
            uint32_t h23 = pack_hi(v.z, v.w, lc, ld);
            uint32_t l01 = pack_lo(la, lb);
            uint32_t l23 = pack_lo(lc, ld);
            uint32_t o = row*XROW + c4*8;
            sts64(sb + XH_OFF + o, h01, h23);
            sts64(sb + XL_OFF + o, l01, l23);
        }
    }

    // ===== GEMM1: Y[64,256] = Xsplit @ At^T, K=256 in 16 chunks =====
    float acc[16][4];
    #pragma unroll
    for (int t = 0; t < 16; ++t)
        #pragma unroll
        for (int r = 0; r < 4; ++r) acc[t][r] = 0.f;

    const uint32_t xh_a = sb + XH_OFF + (m0+qr)*XROW + qc*4;
    const uint32_t xl_a = sb + XL_OFF + (m0+qr)*XROW + qc*4;

    #pragma unroll 1
    for (int k = 0; k < 16; ++k) {
        CP_WAIT0();
        __syncthreads();
        if (k < 15) {
            int e0 = (k+1)*16;
            uint32_t dst = sb + AT_OFF + ((k+1) & 1)*AT_BUF;
            #pragma unroll
            for (int it = 0; it < 2; ++it) {
                int i = tid + it*256;
                int j = i >> 1, half = i & 1;
                uint32_t d = dst + j*48 + half*16;
                CP_ASYNC16(d,         g_At_hi + j*E_ + e0 + half*8);
                CP_ASYNC16(d + AT_LO, g_At_lo + j*E_ + e0 + half*8);
            }
            CP_COMMIT();
        }
        const uint32_t atb = sb + AT_OFF + (k & 1)*AT_BUF;
        const uint32_t e2 = (uint32_t)k * 32;    // e0*2 bytes
        uint32_t a_h[4], a_l[4];
        a_h[0] = lds32(xh_a + e2);
        a_h[1] = lds32(xh_a + e2 + 8*XROW);
        a_h[2] = lds32(xh_a + e2 + 16);
        a_h[3] = lds32(xh_a + e2 + 8*XROW + 16);
        a_l[0] = lds32(xl_a + e2);
        a_l[1] = lds32(xl_a + e2 + 8*XROW);
        a_l[2] = lds32(xl_a + e2 + 16);
        a_l[3] = lds32(xl_a + e2 + 8*XROW + 16);
        #pragma unroll
        for (int nt = 0; nt < 16; ++nt) {
            uint32_t ba = atb + (uint32_t)(nhalf + nt*8 + qr)*48 + qc*4;
            uint32_t bh[2] = { lds32(ba),         lds32(ba + 16) };
            uint32_t bl[2] = { lds32(ba + AT_LO), lds32(ba + AT_LO + 16) };
            mma16816(acc[nt], a_h, bh);
            mma16816(acc[nt], a_h, bl);
            mma16816(acc[nt], a_l, bh);
        }
    }

    // --- split Y to bf16 hi/lo in SMEM ---
    #pragma unroll
    for (int nt = 0; nt < 16; ++nt) {
        int col = nhalf + nt*8 + qc*2;
        float r0, r1, r2, r3;
        uint32_t h01 = pack_hi(acc[nt][0], acc[nt][1], r0, r1);
        uint32_t l01 = pack_lo(r0, r1);
        uint32_t h23 = pack_hi(acc[nt][2], acc[nt][3], r2, r3);
        uint32_t l23 = pack_lo(r2, r3);
        uint32_t a0 = sb + YH_OFF + (uint32_t)(m0+qr)*XROW + col*2;
        sts32(a0, h01);
        sts32(a0 + 8*XROW, h23);
        sts32(a0 + (YL_OFF - YH_OFF), l01);
        sts32(a0 + (YL_OFF - YH_OFF) + 8*XROW, l23);
    }
    __syncthreads();

    // ===== GEMM2: S[64,64] = Ysplit @ Xsplit^T =====
    const int nb = (w >> 2) * 32;
    float s2[4][4];
    #pragma unroll
    for (int t = 0; t < 4; ++t)
        #pragma unroll
        for (int r = 0; r < 4; ++r) s2[t][r] = 0.f;

    const uint32_t yh_a = sb + YH_OFF + (m0+qr)*XROW + qc*4;
    const uint32_t yl_a = sb + YL_OFF + (m0+qr)*XROW + qc*4;

    #pragma unroll 1
    for (int k = 0; k < 16; ++k) {
        const uint32_t j2 = (uint32_t)k * 32;
        uint32_t a_h[4], a_l[4];
        a_h[0] = lds32(yh_a + j2);
        a_h[1] = lds32(yh_a + j2 + 8*XROW);
        a_h[2] = lds32(yh_a + j2 + 16);
        a_h[3] = lds32(yh_a + j2 + 8*XROW + 16);
        a_l[0] = lds32(yl_a + j2);
        a_l[1] = lds32(yl_a + j2 + 8*XROW);
        a_l[2] = lds32(yl_a + j2 + 16);
        a_l[3] = lds32(yl_a + j2 + 8*XROW + 16);
        #pragma unroll
        for (int nt = 0; nt < 4; ++nt) {
            uint32_t ba = sb + XH_OFF + (uint32_t)(nb + nt*8 + qr)*XROW + j2 + qc*4;
            uint32_t bh[2] = { lds32(ba), lds32(ba + 16) };
            uint32_t bl[2] = { lds32(ba + (XL_OFF - XH_OFF)),
                               lds32(ba + (XL_OFF - XH_OFF) + 16) };
            mma16816(s2[nt], a_h, bh);
            mma16816(s2[nt], a_h, bl);
            mma16816(s2[nt], a_l, bh);
        }
    }
    __syncthreads();   // done reading X/Y via GEMM2 before probs overwrite AT area

    // --- scale + mask, dump S to probs buffer (stride 68 f32) ---
    {
        float* probs = (float*)(sm + PROB_OFF);
        int r0i = m0 + qr, r1i = r0i + 8;
        float dl0 = dropf[r0i], dl1 = dropf[r1i];
        #pragma unroll
        for (int nt = 0; nt < 4; ++nt) {
            int c0 = nb + nt*8 + qc*2;
            float dk0 = dropf[c0], dk1 = dropf[c0+1];
            float v00 = s2[nt][0] * 0.0625f;
            float v01 = s2[nt][1] * 0.0625f;
            float v10 = s2[nt][2] * 0.0625f;
            float v11 = s2[nt][3] * 0.0625f;
            if (dl0 != 0.f && dk0 != 0.f) v00 = -1e9f;
            if (dl0 != 0.f && dk1 != 0.f) v01 = -1e9f;
            if (dl1 != 0.f && dk0 != 0.f) v10 = -1e9f;
            if (dl1 != 0.f && dk1 != 0.f) v11 = -1e9f;
            probs[r0i*68 + c0]     = v00;
            probs[r0i*68 + c0 + 1] = v01;
            probs[r1i*68 + c0]     = v10;
            probs[r1i*68 + c0 + 1] = v11;
        }
    }
    __syncthreads();

    // --- softmax over k (4 lanes per row) ---
    {
        float* probs = (float*)(sm + PROB_OFF);
        int r = tid >> 2, part = tid & 3;
        float* Srow = probs + r*68 + (part << 4);
        float m = -1e30f;
        #pragma unroll
        for (int kk = 0; kk < 16; ++kk) m = fmaxf(m, Srow[kk]);
        m = fmaxf(m, __shfl_xor_sync(0xffffffffu, m, 1));
        m = fmaxf(m, __shfl_xor_sync(0xffffffffu, m, 2));
        float ssum = 0.f;
        #pragma unroll
        for (int kk = 0; kk < 16; ++kk) {
            float p = __expf(Srow[kk] - m);
            Srow[kk] = p; ssum += p;
        }
        ssum += __shfl_xor_sync(0xffffffffu, ssum, 1);
        ssum += __shfl_xor_sync(0xffffffffu, ssum, 2);
        if (part == 0) rowinv[r] = 1.f / ssum;
    }
    __syncthreads();

    // --- column sums of probs ---
    {
        float* probs = (float*)(sm + PROB_OFF);
        int k = tid & 63, seg = tid >> 6;
        float p = 0.f;
        #pragma unroll
        for (int li = 0; li < 16; ++li) {
            int l = (seg << 4) + li;
            p = fmaf(probs[l*68 + k], rowinv[l], p);
        }
        atomicAdd(&wsm[k], p);
    }
    __syncthreads();

    // --- z[e] = sum_k w[k] * x[k][e]  (x = hi + lo) ---
    {
        const __nv_bfloat16* xh = (const __nv_bfloat16*)(sm + XH_OFF);
        const __nv_bfloat16* xl = (const __nv_bfloat16*)(sm + XL_OFF);
        const int e = tid;
        float z = 0.f;
        #pragma unroll 8
        for (int k = 0; k < 64; ++k) {
            float xv = __bfloat162float(xh[k*(XROW/2) + e]) +
                       __bfloat162float(xl[k*(XROW/2) + e]);
            z = fmaf(wsm[k], xv, z);
        }
        g_z[(size_t)n*E_ + e] = z;
    }
}

// ---------------------------------------------------------------------------
// hidden[n][f] = sum_j z[n][j] * Ccm[j][f]   (32 n per block)
__global__ __launch_bounds__(256) void hidden_kernel()
{
    __shared__ float zs[32*E_];
    const int nb = blockIdx.x * 32, tid = threadIdx.x;
    for (int i = tid; i < 32*E_; i += 256) zs[i] = g_z[(size_t)nb*E_ + i];
    __syncthreads();
    float acc[32];
    #pragma unroll
    for (int nn = 0; nn < 32; ++nn) acc[nn] = 0.f;
    for (int j = 0; j < E_; ++j) {
        float c = g_Ccm[j*E_ + tid];
        #pragma unroll
        for (int nn = 0; nn < 32; ++nn) acc[nn] = fmaf(zs[nn*E_ + j], c, acc[nn]);
    }
    #pragma unroll
    for (int nn = 0; nn < 32; ++nn) g_hidden[(size_t)(nb + nn)*E_ + tid] = acc[nn];
}

// ---------------------------------------------------------------------------
__global__ __launch_bounds__(128) void lstm_kernel(
    const float* __restrict__ done, const float* __restrict__ h0,
    const float* __restrict__ c0,
    const float* __restrict__ w_ih, const float* __restrict__ w_hh,
    const float* __restrict__ b_ih, const float* __restrict__ b_hh,
    const float* __restrict__ critic_w, const float* __restrict__ critic_b,
    float* __restrict__ out)
{
    extern __shared__ float smf[];
    float* wih  = smf;
    float* whh  = wih + 128*260;
    float* xrow = whh + 128*36;
    float* bias = xrow + 256;
    float* garr = bias + 128;
    float* hsm  = garr + 128;
    float* csm  = hsm + 32;

    const int env = blockIdx.x, tid = threadIdx.x;

    for (int i = tid; i < 128*256; i += 128)
        wih[(i >> 8)*260 + (i & 255)] = w_ih[i];
    for (int i = tid; i < 128*32; i += 128)
        whh[(i >> 5)*36 + (i & 31)] = w_hh[i];
    bias[tid] = b_ih[tid] + b_hh[tid];
    if (tid < 32) { hsm[tid] = h0[env*H_ + tid]; csm[tid] = c0[env*H_ + tid]; }
    const float cw = (tid < 32) ? critic_w[tid] : 0.f;
    const float cb = critic_b[0];
    __syncthreads();

    const float4* wr = (const float4*)(wih + tid*260);
    const float4* wh = (const float4*)(whh + tid*36);

    for (int t = 0; t < T_; ++t) {
        const int row = t*B_ + env;
        const float keep = 1.f - done[row];
        if (tid < 32) { hsm[tid] *= keep; csm[tid] *= keep; }
        {
            const float* hr = g_hidden + (size_t)row*E_;
            xrow[tid]       = hr[tid];
            xrow[tid + 128] = hr[tid + 128];
        }
        __syncthreads();

        float acc = bias[tid];
        const float4* xr = (const float4*)xrow;
        #pragma unroll 8
        for (int e4 = 0; e4 < 64; ++e4) {
            float4 a = wr[e4], b = xr[e4];
            acc = fmaf(a.x, b.x, acc); acc = fmaf(a.y, b.y, acc);
            acc = fmaf(a.z, b.z, acc); acc = fmaf(a.w, b.w, acc);
        }
        const float4* hv = (const float4*)hsm;
        #pragma unroll
        for (int j4 = 0; j4 < 8; ++j4) {
            float4 a = wh[j4], b = hv[j4];
            acc = fmaf(a.x, b.x, acc); acc = fmaf(a.y, b.y, acc);
            acc = fmaf(a.z, b.z, acc); acc = fmaf(a.w, b.w, acc);
        }
        garr[tid] = (tid >= 64 && tid < 96) ? tanhf(acc)
                                            : (1.f / (1.f + __expf(-acc)));
        __syncthreads();

        if (tid < 32) {
            float c = fmaf(garr[32 + tid], csm[tid], garr[tid] * garr[64 + tid]);
            float h = garr[96 + tid] * tanhf(c);
            csm[tid] = c; hsm[tid] = h;
            float p = h * cw;
            p += __shfl_xor_sync(0xffffffffu, p, 16);
            p += __shfl_xor_sync(0xffffffffu, p, 8);
            p += __shfl_xor_sync(0xffffffffu, p, 4);
            p += __shfl_xor_sync(0xffffffffu, p, 2);
            p += __shfl_xor_sync(0xffffffffu, p, 1);
            if (tid == 0) out[row] = p + cb;
        }
        __syncthreads();
    }
}

extern "C" void kernel_launch(void* const* d_in, const int* in_sizes, int n_in,
                              void* d_out, int out_size)
{
    const float* x        = (const float*)d_in[0];
    const float* done     = (const float*)d_in[1];
    const void*  mask     = d_in[2];
    const float* h0       = (const float*)d_in[3];
    const float* c0       = (const float*)d_in[4];
    const float* in_proj  = (const float*)d_in[5];
    const float* out_proj = (const float*)d_in[6];
    const float* w_ih     = (const float*)d_in[7];
    const float* w_hh     = (const float*)d_in[8];
    const float* b_ih     = (const float*)d_in[9];
    const float* b_hh     = (const float*)d_in[10];
    const float* critic_w = (const float*)d_in[11];
    const float* critic_b = (const float*)d_in[12];
    float* out = (float*)d_out;

    cudaFuncSetAttribute(attn_mma_kernel, cudaFuncAttributeMaxDynamicSharedMemorySize, ATTN_SMEM);
    cudaFuncSetAttribute(lstm_kernel, cudaFuncAttributeMaxDynamicSharedMemorySize, LSTM_SMEM);

    detect_mask_kernel<<<1, 256>>>(mask);
    precompute_kernel<<<2*E_, 256>>>(in_proj, out_proj);
    attn_mma_kernel<<<N_, 256, ATTN_SMEM>>>(x, mask);
    hidden_kernel<<<N_/32, 256>>>();
    lstm_kernel<<<B_, 128, LSTM_SMEM>>>(done, h0, c0, w_ih, w_hh, b_ih, b_hh,
                                        critic_w, critic_b, out);
}